// round 3
// baseline (speedup 1.0000x reference)
#include <cuda_runtime.h>

#define NMAX  100000
#define EMAX  1600000
#define HDIM  32

// Scratch (allocation-free rule: __device__ globals)
__device__ int   g_is32;                       // 1 if edge_index is int32
__device__ float g_dis[NMAX];
__device__ int   g_deg[NMAX];
__device__ int   g_src32[EMAX];
__device__ int   g_dst32[EMAX];
__device__ float g_nrm[EMAX];
__device__ float g_tmp[(size_t)NMAX * HDIM];   // h = in @ W (pre-scatter messages)
__device__ float g_acc[(size_t)NMAX * HDIM];   // layer-1 accumulator

// ---------------- dtype detection ----------------
// If the (2,E) index tensor is int64, every 8-byte value is in [0, n).
// If it is int32 (JAX x64-disabled default), an 8-byte read combines two
// indices: lo + hi*2^32, out of range unless hi==0 (p = 1e-5 per sample).

__global__ void detect_kernel(const long long* __restrict__ ei, int e, int n) {
    if (threadIdx.x != 0 || blockIdx.x != 0) return;
    int ok64 = 1;
    for (int i = 0; i < 32; i++) {
        long long a = ei[i];
        long long b = ei[e + i];
        if (a < 0 || a >= n || b < 0 || b >= n) ok64 = 0;
    }
    g_is32 = ok64 ? 0 : 1;
}

// ---------------- degree / normalization / index prep ----------------

__global__ void deg_init_kernel(int n) {
    int i = blockIdx.x * blockDim.x + threadIdx.x;
    if (i < n) g_deg[i] = 1;                    // self-loop
}

// Narrow/copy indices to int32 scratch, count degrees at dst.
__global__ void prep_kernel(const void* __restrict__ ei, int e) {
    int i = blockIdx.x * blockDim.x + threadIdx.x;
    if (i >= e) return;
    int s, d;
    if (g_is32) {
        const int* p = (const int*)ei;
        s = p[i];
        d = p[e + i];
    } else {
        const long long* p = (const long long*)ei;
        s = (int)p[i];
        d = (int)p[e + i];
    }
    g_src32[i] = s;
    g_dst32[i] = d;
    atomicAdd(&g_deg[d], 1);
}

__global__ void dis_kernel(int n) {
    int i = blockIdx.x * blockDim.x + threadIdx.x;
    if (i < n) g_dis[i] = rsqrtf((float)g_deg[i]);
}

__global__ void nrm_kernel(int e) {
    int i = blockIdx.x * blockDim.x + threadIdx.x;
    if (i >= e) return;
    g_nrm[i] = g_dis[g_src32[i]] * g_dis[g_dst32[i]];
}

// ---------------- fused GEMM (+optional bias/ReLU on input) + self-loop init ----------------
// One thread per node row. tmp[node] = rowin @ W ;  acc[node] = tmp[node]*dis^2.

template <bool RELU_BIAS>
__global__ void __launch_bounds__(256)
mm_kernel(const float* __restrict__ in, const float* __restrict__ W,
          const float* __restrict__ b, const float* __restrict__ dis,
          float* __restrict__ tmp, float* __restrict__ acc, int n)
{
    __shared__ float Ws[32][32];
    __shared__ float bs[32];
    int t = threadIdx.x;
    for (int i = t; i < 1024; i += 256) Ws[i >> 5][i & 31] = W[i];
    if (RELU_BIAS && t < 32) bs[t] = b[t];
    __syncthreads();

    int node = blockIdx.x * 256 + t;
    if (node >= n) return;

    float xr[32];
    const float4* xin = reinterpret_cast<const float4*>(in + (size_t)node * HDIM);
#pragma unroll
    for (int q = 0; q < 8; q++) {
        float4 v = xin[q];
        xr[4 * q + 0] = v.x; xr[4 * q + 1] = v.y;
        xr[4 * q + 2] = v.z; xr[4 * q + 3] = v.w;
    }
    if (RELU_BIAS) {
#pragma unroll
        for (int j = 0; j < 32; j++) xr[j] = fmaxf(xr[j] + bs[j], 0.0f);
    }

    float o[32];
#pragma unroll
    for (int j = 0; j < 32; j++) o[j] = 0.0f;
#pragma unroll
    for (int k = 0; k < 32; k++) {
        float xv = xr[k];
#pragma unroll
        for (int j = 0; j < 32; j++) o[j] = fmaf(xv, Ws[k][j], o[j]);
    }

    float d  = dis[node];
    float d2 = d * d;
    float4* tp = reinterpret_cast<float4*>(tmp + (size_t)node * HDIM);
    float4* ap = reinterpret_cast<float4*>(acc + (size_t)node * HDIM);
#pragma unroll
    for (int q = 0; q < 8; q++) {
        float4 tv = make_float4(o[4 * q + 0], o[4 * q + 1], o[4 * q + 2], o[4 * q + 3]);
        tp[q] = tv;
        ap[q] = make_float4(tv.x * d2, tv.y * d2, tv.z * d2, tv.w * d2);
    }
}

// ---------------- edge scatter: out[dst] += tmp[src] * nrm ----------------
// One thread per edge: MLP=8 on the gather, 8 vectorized no-return reductions
// (4x fewer L2 atomic transactions than scalar atomicAdd).

__global__ void __launch_bounds__(256)
scatter_kernel(const float* __restrict__ tmp, float* __restrict__ out, int e)
{
    int i = blockIdx.x * blockDim.x + threadIdx.x;
    if (i >= e) return;
    int s = g_src32[i];
    int d = g_dst32[i];
    float nrm = g_nrm[i];
    const float4* hp = reinterpret_cast<const float4*>(tmp + (size_t)s * HDIM);
    float* op = out + (size_t)d * HDIM;
#pragma unroll
    for (int q = 0; q < 8; q++) {
        float4 v = hp[q];
        v.x *= nrm; v.y *= nrm; v.z *= nrm; v.w *= nrm;
        asm volatile(
            "red.global.add.v4.f32 [%0], {%1, %2, %3, %4};"
            :: "l"(op + 4 * q), "f"(v.x), "f"(v.y), "f"(v.z), "f"(v.w)
            : "memory");
    }
}

// ---------------- finalize: out = relu(out + b) ----------------

__global__ void finalize_kernel(float* __restrict__ out, const float* __restrict__ b, int total) {
    int i = blockIdx.x * blockDim.x + threadIdx.x;
    if (i < total) out[i] = fmaxf(out[i] + __ldg(&b[i & (HDIM - 1)]), 0.0f);
}

// ---------------- launch ----------------

extern "C" void kernel_launch(void* const* d_in, const int* in_sizes, int n_in,
                              void* d_out, int out_size)
{
    const float* x   = (const float*)d_in[0];
    const void*  ei  = d_in[1];
    const float* W1  = (const float*)d_in[2];
    const float* b1  = (const float*)d_in[3];
    const float* W2  = (const float*)d_in[4];
    const float* b2  = (const float*)d_in[5];
    float*       out = (float*)d_out;

    int n = in_sizes[0] / HDIM;       // 100000
    int e = in_sizes[1] / 2;          // 1600000 (element count is width-independent)

    void *p_dis, *p_tmp, *p_acc;
    cudaGetSymbolAddress(&p_dis, g_dis);
    cudaGetSymbolAddress(&p_tmp, g_tmp);
    cudaGetSymbolAddress(&p_acc, g_acc);
    float* dis = (float*)p_dis;
    float* tmp = (float*)p_tmp;
    float* acc = (float*)p_acc;

    int nb_n = (n + 255) / 256;
    int nb_e = (e + 255) / 256;

    // dtype detection + normalization + index prep
    detect_kernel   <<<1, 32>>>((const long long*)ei, e, n);
    deg_init_kernel <<<nb_n, 256>>>(n);
    prep_kernel     <<<nb_e, 256>>>(ei, e);
    dis_kernel      <<<nb_n, 256>>>(n);
    nrm_kernel      <<<nb_e, 256>>>(e);

    // layer 1: tmp = x@W1, acc = self-loop init; scatter edges into acc
    mm_kernel<false><<<nb_n, 256>>>(x, W1, nullptr, dis, tmp, acc, n);
    scatter_kernel  <<<nb_e, 256>>>(tmp, acc, e);

    // layer 2: input = relu(acc + b1) fused into GEMM load; accumulate into d_out
    mm_kernel<true> <<<nb_n, 256>>>(acc, W2, b1, dis, tmp, out, n);
    scatter_kernel  <<<nb_e, 256>>>(tmp, out, e);

    // out = relu(out + b2)
    finalize_kernel <<<(n * HDIM + 255) / 256, 256>>>(out, b2, n * HDIM);
}

// round 4
// speedup vs baseline: 1.6140x; 1.6140x over previous
#include <cuda_runtime.h>

#define NMAX   100000
#define EMAX   1600000
#define HDIM   32
#define SCAN_B 1024
#define NSCANB ((NMAX + SCAN_B - 1) / SCAN_B)   // 98

// Scratch (allocation-free rule: __device__ globals)
__device__ int   g_is32;                       // 1 if edge_index is int32
__device__ int   g_deg[NMAX];                  // real in-degree (excl. self-loop)
__device__ float g_dis[NMAX];                  // rsqrt(deg+1)
__device__ int   g_excl[NMAX];                 // per-block exclusive scan
__device__ int   g_bsum[NSCANB + 1];
__device__ int   g_boff[NSCANB + 1];
__device__ int   g_rowstart[NMAX + 1];         // CSR offsets
__device__ int   g_cursor[NMAX];               // fill cursors
__device__ int2  g_csr[EMAX + 32];             // per in-edge: (src, norm-as-bits)
__device__ float g_tmp[(size_t)NMAX * HDIM];   // h = in @ W
__device__ float g_acc[(size_t)NMAX * HDIM];   // layer-1 output (pre bias/relu)

// ---------------- dtype detection (int32 vs int64 edge index) ----------------

__global__ void detect_kernel(const long long* __restrict__ ei, int e, int n) {
    if (threadIdx.x != 0 || blockIdx.x != 0) return;
    int ok64 = 1;
    for (int i = 0; i < 32; i++) {
        long long a = ei[i];
        long long b = ei[e + i];
        if (a < 0 || a >= n || b < 0 || b >= n) ok64 = 0;
    }
    g_is32 = ok64 ? 0 : 1;
}

// ---------------- degree / normalization ----------------

__global__ void deg_zero_kernel(int n) {
    int i = blockIdx.x * blockDim.x + threadIdx.x;
    if (i < n) g_deg[i] = 0;
}

__global__ void count_kernel(const void* __restrict__ ei, int e) {
    int i = blockIdx.x * blockDim.x + threadIdx.x;
    if (i >= e) return;
    int d = g_is32 ? ((const int*)ei)[e + i]
                   : (int)((const long long*)ei)[e + i];
    atomicAdd(&g_deg[d], 1);
}

__global__ void dis_kernel(int n) {
    int i = blockIdx.x * blockDim.x + threadIdx.x;
    if (i < n) g_dis[i] = rsqrtf((float)(g_deg[i] + 1));   // +1: self-loop
}

// ---------------- exclusive scan of degrees -> CSR offsets ----------------

__global__ void scan1_kernel(int n) {
    __shared__ int sm[SCAN_B];
    int t = threadIdx.x;
    int i = blockIdx.x * SCAN_B + t;
    int v = (i < n) ? g_deg[i] : 0;
    sm[t] = v;
    __syncthreads();
    for (int off = 1; off < SCAN_B; off <<= 1) {
        int add = (t >= off) ? sm[t - off] : 0;
        __syncthreads();
        sm[t] += add;
        __syncthreads();
    }
    if (i < n) g_excl[i] = sm[t] - v;
    if (t == SCAN_B - 1) g_bsum[blockIdx.x] = sm[t];
}

__global__ void scan2_kernel(int nb) {
    __shared__ int sm[128];
    int t = threadIdx.x;
    int v = (t < nb) ? g_bsum[t] : 0;
    sm[t] = v;
    __syncthreads();
    for (int off = 1; off < 128; off <<= 1) {
        int add = (t >= off) ? sm[t - off] : 0;
        __syncthreads();
        sm[t] += add;
        __syncthreads();
    }
    if (t < nb) g_boff[t] = sm[t] - v;
}

__global__ void scan3_kernel(int n, int e) {
    int i = blockIdx.x * blockDim.x + threadIdx.x;
    if (i < n) {
        int r = g_excl[i] + g_boff[i / SCAN_B];
        g_rowstart[i] = r;
        g_cursor[i]   = r;
    }
    if (i == n) g_rowstart[n] = e;
}

// ---------------- CSR fill: edge -> (src, dis[src]*dis[dst]) at dst's slot ----------------

__global__ void fill_kernel(const void* __restrict__ ei, int e) {
    int i = blockIdx.x * blockDim.x + threadIdx.x;
    if (i >= e) return;
    int s, d;
    if (g_is32) {
        const int* p = (const int*)ei;
        s = p[i]; d = p[e + i];
    } else {
        const long long* p = (const long long*)ei;
        s = (int)p[i]; d = (int)p[e + i];
    }
    int pos = atomicAdd(&g_cursor[d], 1);
    g_csr[pos] = make_int2(s, __float_as_int(g_dis[s] * g_dis[d]));
}

// ---------------- fused GEMM (+optional bias/ReLU on input) ----------------
// One thread per node row: tmp[node] = f(rowin) @ W.

template <bool RELU_BIAS>
__global__ void __launch_bounds__(256)
mm_kernel(const float* __restrict__ in, const float* __restrict__ W,
          const float* __restrict__ b, float* __restrict__ tmp, int n)
{
    __shared__ float Ws[32][32];
    __shared__ float bs[32];
    int t = threadIdx.x;
    for (int i = t; i < 1024; i += 256) Ws[i >> 5][i & 31] = W[i];
    if (RELU_BIAS && t < 32) bs[t] = b[t];
    __syncthreads();

    int node = blockIdx.x * 256 + t;
    if (node >= n) return;

    float xr[32];
    const float4* xin = reinterpret_cast<const float4*>(in + (size_t)node * HDIM);
#pragma unroll
    for (int q = 0; q < 8; q++) {
        float4 v = xin[q];
        xr[4 * q + 0] = v.x; xr[4 * q + 1] = v.y;
        xr[4 * q + 2] = v.z; xr[4 * q + 3] = v.w;
    }
    if (RELU_BIAS) {
#pragma unroll
        for (int j = 0; j < 32; j++) xr[j] = fmaxf(xr[j] + bs[j], 0.0f);
    }

    float o[32];
#pragma unroll
    for (int j = 0; j < 32; j++) o[j] = 0.0f;
#pragma unroll
    for (int k = 0; k < 32; k++) {
        float xv = xr[k];
#pragma unroll
        for (int j = 0; j < 32; j++) o[j] = fmaf(xv, Ws[k][j], o[j]);
    }

    float4* tp = reinterpret_cast<float4*>(tmp + (size_t)node * HDIM);
#pragma unroll
    for (int q = 0; q < 8; q++)
        tp[q] = make_float4(o[4 * q + 0], o[4 * q + 1], o[4 * q + 2], o[4 * q + 3]);
}

// ---------------- aggregate (pure gather, no atomics) ----------------
// Warp per node, lane = feature. Batch-load 32 edges' metadata per lane,
// shfl-broadcast, coalesced 128B row gathers with MLP ~= degree.

template <bool RELU_BIAS>
__global__ void __launch_bounds__(256)
agg_kernel(const float* __restrict__ tmp, float* __restrict__ out,
           const float* __restrict__ b, int n)
{
    int warp = (blockIdx.x * 256 + threadIdx.x) >> 5;
    int lane = threadIdx.x & 31;
    if (warp >= n) return;
    int node  = warp;
    int start = g_rowstart[node];
    int end   = g_rowstart[node + 1];

    float dn = g_dis[node];
    float a  = tmp[(size_t)node * HDIM + lane] * dn * dn;   // self-loop term

    for (int k = start; k < end; k += 32) {
        int idx  = k + lane;
        int2 ed  = g_csr[idx < end ? idx : (end - 1)];
        float wf = __int_as_float(ed.y);
        int cnt  = end - k;
#pragma unroll
        for (int j = 0; j < 32; j++) {
            int   ss = __shfl_sync(0xffffffffu, ed.x, j);
            float ww = __shfl_sync(0xffffffffu, wf, j);
            if (j < cnt)
                a = fmaf(ww, __ldg(&tmp[(size_t)ss * HDIM + lane]), a);
        }
    }

    if (RELU_BIAS) a = fmaxf(a + __ldg(&b[lane]), 0.0f);
    out[(size_t)node * HDIM + lane] = a;
}

// ---------------- launch ----------------

extern "C" void kernel_launch(void* const* d_in, const int* in_sizes, int n_in,
                              void* d_out, int out_size)
{
    const float* x   = (const float*)d_in[0];
    const void*  ei  = d_in[1];
    const float* W1  = (const float*)d_in[2];
    const float* b1  = (const float*)d_in[3];
    const float* W2  = (const float*)d_in[4];
    const float* b2  = (const float*)d_in[5];
    float*       out = (float*)d_out;

    int n = in_sizes[0] / HDIM;       // 100000
    int e = in_sizes[1] / 2;          // 1600000

    void *p_tmp, *p_acc;
    cudaGetSymbolAddress(&p_tmp, g_tmp);
    cudaGetSymbolAddress(&p_acc, g_acc);
    float* tmp = (float*)p_tmp;
    float* acc = (float*)p_acc;

    int nb_n  = (n + 255) / 256;
    int nb_n1 = (n + 256) / 256;              // covers index n for rowstart[n]
    int nb_e  = (e + 255) / 256;
    int nb_s  = (n + SCAN_B - 1) / SCAN_B;    // 98
    int nb_w  = (n * 32 + 255) / 256;         // warp-per-node grids

    // normalization + CSR build (amortized over both layers)
    detect_kernel   <<<1, 32>>>((const long long*)ei, e, n);
    deg_zero_kernel <<<nb_n, 256>>>(n);
    count_kernel    <<<nb_e, 256>>>(ei, e);
    dis_kernel      <<<nb_n, 256>>>(n);
    scan1_kernel    <<<nb_s, SCAN_B>>>(n);
    scan2_kernel    <<<1, 128>>>(nb_s);
    scan3_kernel    <<<nb_n1, 256>>>(n, e);
    fill_kernel     <<<nb_e, 256>>>(ei, e);

    // layer 1
    mm_kernel<false> <<<nb_n, 256>>>(x, W1, nullptr, tmp, n);
    agg_kernel<false><<<nb_w, 256>>>(tmp, acc, nullptr, n);

    // layer 2 (b1+ReLU fused into GEMM load; b2+ReLU fused into agg epilogue)
    mm_kernel<true>  <<<nb_n, 256>>>(acc, W2, b1, tmp, n);
    agg_kernel<true> <<<nb_w, 256>>>(tmp, out, b2, n);
}

// round 5
// speedup vs baseline: 1.7705x; 1.0970x over previous
#include <cuda_runtime.h>
#include <cuda_fp16.h>

#define NMAX   100000
#define EMAX   1600000
#define HDIM   32
#define SCAN_B 1024
#define NSCANB ((NMAX + SCAN_B - 1) / SCAN_B)   // 98

// Scratch (allocation-free rule: __device__ globals)
__device__ int    g_is32;                      // 1 if edge_index is int32
__device__ int    g_deg[NMAX];                 // in-degree (excl. self-loop)
__device__ float  g_dis[NMAX];                 // rsqrt(deg+1)
__device__ int    g_excl[NMAX];
__device__ int    g_bsum[NSCANB + 1];
__device__ int    g_boff[NSCANB + 1];
__device__ int    g_rowstart[NMAX + 1];        // CSR offsets
__device__ int    g_cursor[NMAX];              // fill cursors
__device__ int    g_csr[EMAX + 32];            // per in-edge: src only
__device__ __half g_tmp[(size_t)NMAX * HDIM];  // dis[i] * (f(in_i) @ W), fp16
__device__ float  g_acc[(size_t)NMAX * HDIM];  // layer-1 output (pre bias/relu)

// ---------------- dtype detection (int32 vs int64 edge index) ----------------
// int64 read of an int32 buffer fuses two indices -> out of [0,n) w.h.p.

__global__ void detect_kernel(const long long* __restrict__ ei, int e, int n) {
    int i = threadIdx.x;
    long long a = ei[i];
    long long b = ei[e + i];
    bool bad = (a < 0 || a >= n || b < 0 || b >= n);
    unsigned m = __ballot_sync(0xffffffffu, bad);
    if (i == 0) g_is32 = m ? 1 : 0;
}

// ---------------- degree count ----------------

__global__ void count_kernel(const void* __restrict__ ei, int e) {
    int i = blockIdx.x * blockDim.x + threadIdx.x;
    if (i >= e) return;
    int d = g_is32 ? ((const int*)ei)[e + i]
                   : (int)((const long long*)ei)[e + i];
    atomicAdd(&g_deg[d], 1);
}

// ---------------- scan of degrees -> CSR offsets (+ dis fused) ----------------

__global__ void scan1_kernel(int n) {
    __shared__ int sm[SCAN_B];
    int t = threadIdx.x;
    int i = blockIdx.x * SCAN_B + t;
    int v = (i < n) ? g_deg[i] : 0;
    if (i < n) g_dis[i] = rsqrtf((float)(v + 1));   // +1: self-loop
    sm[t] = v;
    __syncthreads();
    for (int off = 1; off < SCAN_B; off <<= 1) {
        int add = (t >= off) ? sm[t - off] : 0;
        __syncthreads();
        sm[t] += add;
        __syncthreads();
    }
    if (i < n) g_excl[i] = sm[t] - v;
    if (t == SCAN_B - 1) g_bsum[blockIdx.x] = sm[t];
}

__global__ void scan2_kernel(int nb) {
    __shared__ int sm[128];
    int t = threadIdx.x;
    int v = (t < nb) ? g_bsum[t] : 0;
    sm[t] = v;
    __syncthreads();
    for (int off = 1; off < 128; off <<= 1) {
        int add = (t >= off) ? sm[t - off] : 0;
        __syncthreads();
        sm[t] += add;
        __syncthreads();
    }
    if (t < nb) g_boff[t] = sm[t] - v;
}

__global__ void scan3_kernel(int n, int e) {
    int i = blockIdx.x * blockDim.x + threadIdx.x;
    if (i < n) {
        int r = g_excl[i] + g_boff[i / SCAN_B];
        g_rowstart[i] = r;
        g_cursor[i]   = r;
    }
    if (i == n) g_rowstart[n] = e;
}

// ---------------- CSR fill: src index into dst's slot ----------------

__global__ void fill_kernel(const void* __restrict__ ei, int e) {
    int i = blockIdx.x * blockDim.x + threadIdx.x;
    if (i >= e) return;
    int s, d;
    if (g_is32) {
        const int* p = (const int*)ei;
        s = p[i]; d = p[e + i];
    } else {
        const long long* p = (const long long*)ei;
        s = (int)p[i]; d = (int)p[e + i];
    }
    int pos = atomicAdd(&g_cursor[d], 1);
    g_csr[pos] = s;
}

// ---------------- fused GEMM: tmp[node] = dis[node] * (f(rowin) @ W), fp16 ----------------

template <bool RELU_BIAS>
__global__ void __launch_bounds__(256)
mm_kernel(const float* __restrict__ in, const float* __restrict__ W,
          const float* __restrict__ b, const float* __restrict__ dis,
          __half* __restrict__ tmp, int n)
{
    __shared__ float Ws[32][32];
    __shared__ float bs[32];
    int t = threadIdx.x;
    for (int i = t; i < 1024; i += 256) Ws[i >> 5][i & 31] = W[i];
    if (RELU_BIAS && t < 32) bs[t] = b[t];
    __syncthreads();

    int node = blockIdx.x * 256 + t;
    if (node >= n) return;

    float xr[32];
    const float4* xin = reinterpret_cast<const float4*>(in + (size_t)node * HDIM);
#pragma unroll
    for (int q = 0; q < 8; q++) {
        float4 v = xin[q];
        xr[4 * q + 0] = v.x; xr[4 * q + 1] = v.y;
        xr[4 * q + 2] = v.z; xr[4 * q + 3] = v.w;
    }
    if (RELU_BIAS) {
#pragma unroll
        for (int j = 0; j < 32; j++) xr[j] = fmaxf(xr[j] + bs[j], 0.0f);
    }

    float o[32];
#pragma unroll
    for (int j = 0; j < 32; j++) o[j] = 0.0f;
#pragma unroll
    for (int k = 0; k < 32; k++) {
        float xv = xr[k];
#pragma unroll
        for (int j = 0; j < 32; j++) o[j] = fmaf(xv, Ws[k][j], o[j]);
    }

    float d = dis[node];
    uint4 u[4];
#pragma unroll
    for (int q = 0; q < 4; q++) {
        __half2 h0 = __floats2half2_rn(o[8 * q + 0] * d, o[8 * q + 1] * d);
        __half2 h1 = __floats2half2_rn(o[8 * q + 2] * d, o[8 * q + 3] * d);
        __half2 h2 = __floats2half2_rn(o[8 * q + 4] * d, o[8 * q + 5] * d);
        __half2 h3 = __floats2half2_rn(o[8 * q + 6] * d, o[8 * q + 7] * d);
        u[q].x = *reinterpret_cast<unsigned*>(&h0);
        u[q].y = *reinterpret_cast<unsigned*>(&h1);
        u[q].z = *reinterpret_cast<unsigned*>(&h2);
        u[q].w = *reinterpret_cast<unsigned*>(&h3);
    }
    uint4* tp = reinterpret_cast<uint4*>(tmp + (size_t)node * HDIM);
#pragma unroll
    for (int q = 0; q < 4; q++) tp[q] = u[q];
}

// ---------------- aggregate (pure gather, no atomics) ----------------
// Warp per node, lane = feature. out[d] = dis[d]*(tmp[d] + sum_src tmp[src]).

template <bool RELU_BIAS>
__global__ void __launch_bounds__(256)
agg_kernel(const __half* __restrict__ tmp, float* __restrict__ out,
           const float* __restrict__ b, int n)
{
    int warp = (blockIdx.x * 256 + threadIdx.x) >> 5;
    int lane = threadIdx.x & 31;
    if (warp >= n) return;
    int node  = warp;
    int start = g_rowstart[node];
    int end   = g_rowstart[node + 1];

    float a = __half2float(__ldg(&tmp[(size_t)node * HDIM + lane]));  // self-loop

    for (int k = start; k < end; k += 32) {
        int idx  = k + lane;
        int mysrc = g_csr[idx < end ? idx : (end - 1)];
        int cnt  = end - k;
#pragma unroll
        for (int j = 0; j < 32; j++) {
            int ss = __shfl_sync(0xffffffffu, mysrc, j);
            if (j < cnt)
                a += __half2float(__ldg(&tmp[(size_t)ss * HDIM + lane]));
        }
    }

    float r = a * g_dis[node];
    if (RELU_BIAS) r = fmaxf(r + __ldg(&b[lane]), 0.0f);
    out[(size_t)node * HDIM + lane] = r;
}

// ---------------- launch ----------------

extern "C" void kernel_launch(void* const* d_in, const int* in_sizes, int n_in,
                              void* d_out, int out_size)
{
    const float* x   = (const float*)d_in[0];
    const void*  ei  = d_in[1];
    const float* W1  = (const float*)d_in[2];
    const float* b1  = (const float*)d_in[3];
    const float* W2  = (const float*)d_in[4];
    const float* b2  = (const float*)d_in[5];
    float*       out = (float*)d_out;

    int n = in_sizes[0] / HDIM;       // 100000
    int e = in_sizes[1] / 2;          // 1600000

    void *p_tmp, *p_acc, *p_deg, *p_dis;
    cudaGetSymbolAddress(&p_tmp, g_tmp);
    cudaGetSymbolAddress(&p_acc, g_acc);
    cudaGetSymbolAddress(&p_deg, g_deg);
    cudaGetSymbolAddress(&p_dis, g_dis);
    __half* tmp = (__half*)p_tmp;
    float*  acc = (float*)p_acc;
    float*  dis = (float*)p_dis;

    int nb_n  = (n + 255) / 256;
    int nb_n1 = (n + 256) / 256;              // covers index n for rowstart[n]
    int nb_e  = (e + 255) / 256;
    int nb_s  = (n + SCAN_B - 1) / SCAN_B;    // 98
    int nb_w  = (n * 32 + 255) / 256;         // warp-per-node grids

    // normalization + CSR build
    detect_kernel <<<1, 32>>>((const long long*)ei, e, n);
    cudaMemsetAsync(p_deg, 0, (size_t)n * sizeof(int));
    count_kernel  <<<nb_e, 256>>>(ei, e);
    scan1_kernel  <<<nb_s, SCAN_B>>>(n);
    scan2_kernel  <<<1, 128>>>(nb_s);
    scan3_kernel  <<<nb_n1, 256>>>(n, e);
    fill_kernel   <<<nb_e, 256>>>(ei, e);

    // layer 1
    mm_kernel<false> <<<nb_n, 256>>>(x, W1, nullptr, dis, tmp, n);
    agg_kernel<false><<<nb_w, 256>>>(tmp, acc, nullptr, n);

    // layer 2 (b1+ReLU fused into GEMM load; b2+ReLU fused into agg epilogue)
    mm_kernel<true>  <<<nb_n, 256>>>(acc, W2, b1, dis, tmp, n);
    agg_kernel<true> <<<nb_w, 256>>>(tmp, out, b2, n);
}

// round 6
// speedup vs baseline: 2.2308x; 1.2600x over previous
#include <cuda_runtime.h>
#include <cuda_fp16.h>

#define NMAX   100000
#define EMAX   1600000
#define HDIM   32
#define SCAN_B 1024
#define NSCANB ((NMAX + SCAN_B - 1) / SCAN_B)   // 98

// Scratch (allocation-free rule: __device__ globals)
__device__ int    g_is32;                      // 1 if edge_index is int32
__device__ int    g_deg[NMAX];                 // in-degree (excl. self-loop)
__device__ float  g_dis[NMAX];                 // rsqrt(deg+1)
__device__ int    g_excl[NMAX];                // intra-block exclusive scan
__device__ int    g_bsum[128];                 // per-scan-block sums
__device__ int    g_rowstart[NMAX + 1];        // CSR offsets
__device__ int    g_cursor[NMAX];              // fill cursors
__device__ int    g_csr[EMAX + 32];            // per in-edge: src only
__device__ __half g_tmp[(size_t)NMAX * HDIM];  // dis[i] * (f(in_i) @ W), fp16
__device__ float  g_acc[(size_t)NMAX * HDIM];  // layer-1 output (pre bias/relu)

// ---------------- detect dtype + zero degrees (fused) ----------------
// int64 read of an int32 buffer fuses two indices -> out of [0,n) w.h.p.
// Samples only the first 32 int64 slots (in-bounds for both widths).

__global__ void detect_zero_kernel(const long long* __restrict__ ei, int n) {
    int i = blockIdx.x * blockDim.x + threadIdx.x;
    if (i < n) g_deg[i] = 0;
    if (blockIdx.x == 0 && threadIdx.x < 32) {
        long long a = ei[threadIdx.x];
        bool bad = (a < 0 || a >= n);
        unsigned m = __ballot_sync(0xffffffffu, bad);
        if (threadIdx.x == 0) g_is32 = m ? 1 : 0;
    }
}

// ---------------- degree count ----------------

__global__ void count_kernel(const void* __restrict__ ei, int e) {
    int i = blockIdx.x * blockDim.x + threadIdx.x;
    if (i >= e) return;
    int d = g_is32 ? ((const int*)ei)[e + i]
                   : (int)((const long long*)ei)[e + i];
    atomicAdd(&g_deg[d], 1);
}

// ---------------- scan stage 1: intra-block scan + dis ----------------

__global__ void scan1_kernel(int n) {
    __shared__ int sm[SCAN_B];
    int t = threadIdx.x;
    int i = blockIdx.x * SCAN_B + t;
    int v = (i < n) ? g_deg[i] : 0;
    if (i < n) g_dis[i] = rsqrtf((float)(v + 1));   // +1: self-loop
    sm[t] = v;
    __syncthreads();
    for (int off = 1; off < SCAN_B; off <<= 1) {
        int add = (t >= off) ? sm[t - off] : 0;
        __syncthreads();
        sm[t] += add;
        __syncthreads();
    }
    if (i < n) g_excl[i] = sm[t] - v;
    if (t == SCAN_B - 1) g_bsum[blockIdx.x] = sm[t];
}

// ---------------- scan stage 2+3 fused: every block redundantly scans the
// tiny block-sum array in smem, then emits rowstart/cursor for its nodes.

__global__ void scan23_kernel(int n, int e, int nb) {
    __shared__ int sm[128];
    int t = threadIdx.x;
    if (t < 128) sm[t] = (t < nb) ? g_bsum[t] : 0;
    __syncthreads();
    for (int off = 1; off < 128; off <<= 1) {
        int add = (t < 128 && t >= off) ? sm[t - off] : 0;
        __syncthreads();
        if (t < 128) sm[t] += add;
        __syncthreads();
    }
    // sm now holds inclusive sums; exclusive prefix for block j is sm[j]-bsum... 
    // recompute exclusive: shift via second shared pass
    __shared__ int ex[128];
    if (t < 128) ex[t] = (t == 0) ? 0 : sm[t - 1];
    __syncthreads();

    int i = blockIdx.x * blockDim.x + t;
    if (i < n) {
        int r = g_excl[i] + ex[i >> 10];
        g_rowstart[i] = r;
        g_cursor[i]   = r;
    }
    if (i == n) g_rowstart[n] = e;
}

// ---------------- CSR fill: src index into dst's slot ----------------

__global__ void fill_kernel(const void* __restrict__ ei, int e) {
    int i = blockIdx.x * blockDim.x + threadIdx.x;
    if (i >= e) return;
    int s, d;
    if (g_is32) {
        const int* p = (const int*)ei;
        s = p[i]; d = p[e + i];
    } else {
        const long long* p = (const long long*)ei;
        s = (int)p[i]; d = (int)p[e + i];
    }
    int pos = atomicAdd(&g_cursor[d], 1);
    g_csr[pos] = s;
}

// ---------------- fused GEMM: tmp[node] = dis[node] * (f(rowin) @ W), fp16 ----------------

template <bool RELU_BIAS>
__global__ void __launch_bounds__(256)
mm_kernel(const float* __restrict__ in, const float* __restrict__ W,
          const float* __restrict__ b, const float* __restrict__ dis,
          __half* __restrict__ tmp, int n)
{
    __shared__ float Ws[32][32];
    __shared__ float bs[32];
    int t = threadIdx.x;
    for (int i = t; i < 1024; i += 256) Ws[i >> 5][i & 31] = W[i];
    if (RELU_BIAS && t < 32) bs[t] = b[t];
    __syncthreads();

    int node = blockIdx.x * 256 + t;
    if (node >= n) return;

    float xr[32];
    const float4* xin = reinterpret_cast<const float4*>(in + (size_t)node * HDIM);
#pragma unroll
    for (int q = 0; q < 8; q++) {
        float4 v = xin[q];
        xr[4 * q + 0] = v.x; xr[4 * q + 1] = v.y;
        xr[4 * q + 2] = v.z; xr[4 * q + 3] = v.w;
    }
    if (RELU_BIAS) {
#pragma unroll
        for (int j = 0; j < 32; j++) xr[j] = fmaxf(xr[j] + bs[j], 0.0f);
    }

    float o[32];
#pragma unroll
    for (int j = 0; j < 32; j++) o[j] = 0.0f;
#pragma unroll
    for (int k = 0; k < 32; k++) {
        float xv = xr[k];
#pragma unroll
        for (int j = 0; j < 32; j++) o[j] = fmaf(xv, Ws[k][j], o[j]);
    }

    float d = dis[node];
    uint4 u[4];
#pragma unroll
    for (int q = 0; q < 4; q++) {
        __half2 h0 = __floats2half2_rn(o[8 * q + 0] * d, o[8 * q + 1] * d);
        __half2 h1 = __floats2half2_rn(o[8 * q + 2] * d, o[8 * q + 3] * d);
        __half2 h2 = __floats2half2_rn(o[8 * q + 4] * d, o[8 * q + 5] * d);
        __half2 h3 = __floats2half2_rn(o[8 * q + 6] * d, o[8 * q + 7] * d);
        u[q].x = *reinterpret_cast<unsigned*>(&h0);
        u[q].y = *reinterpret_cast<unsigned*>(&h1);
        u[q].z = *reinterpret_cast<unsigned*>(&h2);
        u[q].w = *reinterpret_cast<unsigned*>(&h3);
    }
    uint4* tp = reinterpret_cast<uint4*>(tmp + (size_t)node * HDIM);
#pragma unroll
    for (int q = 0; q < 4; q++) tp[q] = u[q];
}

// ---------------- aggregate (pure gather, no atomics) ----------------
// 2 nodes per warp: 16-lane group per node, lane = 2 features (half2).
// out[d] = dis[d] * (tmp[d] + sum_src tmp[src]).  16-wide edge batches match
// the average degree, halving wasted unroll slots vs 32-wide.

template <bool RELU_BIAS>
__global__ void __launch_bounds__(256)
agg_kernel(const __half2* __restrict__ tmp2, float* __restrict__ out,
           const float* __restrict__ b, int n)
{
    int gid  = blockIdx.x * 256 + threadIdx.x;
    int node = gid >> 4;                 // 16 lanes per node
    int li   = threadIdx.x & 15;
    if (node >= n) return;

    int start = g_rowstart[node];
    int end   = g_rowstart[node + 1];

    float2 a = __half22float2(__ldg(&tmp2[(size_t)node * 16 + li]));  // self-loop

    for (int k = start; k < end; k += 16) {
        int idx = k + li;
        int src = g_csr[idx < end ? idx : (end - 1)];
        int cnt = end - k;
#pragma unroll
        for (int j = 0; j < 16; j++) {
            int ss = __shfl_sync(0xffffffffu, src, j, 16);   // within 16-lane segment
            if (j < cnt) {
                float2 v = __half22float2(__ldg(&tmp2[(size_t)ss * 16 + li]));
                a.x += v.x;
                a.y += v.y;
            }
        }
    }

    float dn = g_dis[node];
    a.x *= dn;
    a.y *= dn;
    if (RELU_BIAS) {
        float2 bb = reinterpret_cast<const float2*>(b)[li];
        a.x = fmaxf(a.x + bb.x, 0.0f);
        a.y = fmaxf(a.y + bb.y, 0.0f);
    }
    reinterpret_cast<float2*>(out)[(size_t)node * 16 + li] = a;
}

// ---------------- launch ----------------

extern "C" void kernel_launch(void* const* d_in, const int* in_sizes, int n_in,
                              void* d_out, int out_size)
{
    const float* x   = (const float*)d_in[0];
    const void*  ei  = d_in[1];
    const float* W1  = (const float*)d_in[2];
    const float* b1  = (const float*)d_in[3];
    const float* W2  = (const float*)d_in[4];
    const float* b2  = (const float*)d_in[5];
    float*       out = (float*)d_out;

    int n = in_sizes[0] / HDIM;       // 100000
    int e = in_sizes[1] / 2;          // 1600000

    void *p_tmp, *p_acc, *p_dis;
    cudaGetSymbolAddress(&p_tmp, g_tmp);
    cudaGetSymbolAddress(&p_acc, g_acc);
    cudaGetSymbolAddress(&p_dis, g_dis);
    __half2* tmp2 = (__half2*)p_tmp;
    __half*  tmp  = (__half*)p_tmp;
    float*   acc  = (float*)p_acc;
    float*   dis  = (float*)p_dis;

    int nb_n  = (n + 255) / 256;
    int nb_n1 = (n + 256) / 256;              // covers index n for rowstart[n]
    int nb_e  = (e + 255) / 256;
    int nb_s  = (n + SCAN_B - 1) / SCAN_B;    // 98
    int nb_h  = (n * 16 + 255) / 256;         // 16 lanes per node

    // CSR build + normalization (amortized over both layers)
    detect_zero_kernel<<<nb_n, 256>>>((const long long*)ei, n);
    count_kernel      <<<nb_e, 256>>>(ei, e);
    scan1_kernel      <<<nb_s, SCAN_B>>>(n);
    scan23_kernel     <<<nb_n1, 256>>>(n, e, nb_s);
    fill_kernel       <<<nb_e, 256>>>(ei, e);

    // layer 1
    mm_kernel<false> <<<nb_n, 256>>>(x, W1, nullptr, dis, tmp, n);
    agg_kernel<false><<<nb_h, 256>>>(tmp2, acc, nullptr, n);

    // layer 2 (b1+ReLU fused into GEMM load; b2+ReLU fused into agg epilogue)
    mm_kernel<true>  <<<nb_n, 256>>>(acc, W2, b1, dis, tmp, n);
    agg_kernel<true> <<<nb_h, 256>>>(tmp2, out, b2, n);
}

// round 7
// speedup vs baseline: 2.6097x; 1.1699x over previous
#include <cuda_runtime.h>
#include <cuda_fp16.h>

#define NMAX   100000
#define EMAX   1600000
#define HDIM   32
#define SCAN_B 1024

// Scratch (allocation-free rule: __device__ globals).
// g_deg invariant: zero at every kernel_launch entry (module-load zero-init;
// scan1 re-zeroes after consuming it each call).
__device__ int    g_deg[NMAX];                 // in-degree (excl. self-loop)
__device__ float  g_dis[NMAX];                 // rsqrt(deg+1)
__device__ int    g_excl[NMAX];                // intra-block exclusive scan
__device__ int    g_bsum[128];                 // per-scan-block sums
__device__ int    g_rowstart[NMAX + 1];        // CSR offsets
__device__ int    g_cursor[NMAX];              // fill cursors
__device__ int    g_csr[EMAX + 32];            // per in-edge: src only
__device__ __half g_tmp[(size_t)NMAX * HDIM];  // dis[i] * (f(in_i) @ W), fp16
__device__ float  g_acc[(size_t)NMAX * HDIM];  // layer-1 output (pre bias/relu)

// int64 read of an int32 buffer fuses two indices -> out of [0,n) w.h.p.
// Per-block redundant detection from the first 32 int64 slots (in-bounds for
// both widths since 2E >= 64 int32 elements).
__device__ __forceinline__ int detect_is32(const void* ei, int n, int* s_is32) {
    if (threadIdx.x < 32) {
        long long v = ((const long long*)ei)[threadIdx.x];
        unsigned m = __ballot_sync(0xffffffffu, v < 0 || v >= (long long)n);
        if (threadIdx.x == 0) *s_is32 = m ? 1 : 0;
    }
    __syncthreads();
    return *s_is32;
}

// ---------------- degree count (self-detecting dtype) ----------------

__global__ void count_kernel(const void* __restrict__ ei, int e, int n) {
    __shared__ int s_is32;
    int is32 = detect_is32(ei, n, &s_is32);
    int i = blockIdx.x * blockDim.x + threadIdx.x;
    if (i >= e) return;
    int d = is32 ? ((const int*)ei)[e + i]
                 : (int)((const long long*)ei)[e + i];
    atomicAdd(&g_deg[d], 1);
}

// ---------------- scan stage 1: intra-block scan + dis + deg re-zero ----------------

__global__ void scan1_kernel(int n) {
    __shared__ int sm[SCAN_B];
    int t = threadIdx.x;
    int i = blockIdx.x * SCAN_B + t;
    int v = (i < n) ? g_deg[i] : 0;
    if (i < n) {
        g_dis[i] = rsqrtf((float)(v + 1));   // +1: self-loop
        g_deg[i] = 0;                        // restore invariant for next call
    }
    sm[t] = v;
    __syncthreads();
    for (int off = 1; off < SCAN_B; off <<= 1) {
        int add = (t >= off) ? sm[t - off] : 0;
        __syncthreads();
        sm[t] += add;
        __syncthreads();
    }
    if (i < n) g_excl[i] = sm[t] - v;
    if (t == SCAN_B - 1) g_bsum[blockIdx.x] = sm[t];
}

// ---------------- scan stage 2+3 fused: every block redundantly scans the
// tiny block-sum array in smem, then emits rowstart/cursor for its nodes.

__global__ void scan23_kernel(int n, int e, int nb) {
    __shared__ int sm[128];
    __shared__ int ex[128];
    int t = threadIdx.x;
    if (t < 128) sm[t] = (t < nb) ? g_bsum[t] : 0;
    __syncthreads();
    for (int off = 1; off < 128; off <<= 1) {
        int add = (t < 128 && t >= off) ? sm[t - off] : 0;
        __syncthreads();
        if (t < 128) sm[t] += add;
        __syncthreads();
    }
    if (t < 128) ex[t] = (t == 0) ? 0 : sm[t - 1];
    __syncthreads();

    int i = blockIdx.x * blockDim.x + t;
    if (i < n) {
        int r = g_excl[i] + ex[i >> 10];
        g_rowstart[i] = r;
        g_cursor[i]   = r;
    }
    if (i == n) g_rowstart[n] = e;
}

// ---------------- CSR fill: src index into dst's slot ----------------

__global__ void fill_kernel(const void* __restrict__ ei, int e, int n) {
    __shared__ int s_is32;
    int is32 = detect_is32(ei, n, &s_is32);
    int i = blockIdx.x * blockDim.x + threadIdx.x;
    if (i >= e) return;
    int s, d;
    if (is32) {
        const int* p = (const int*)ei;
        s = p[i]; d = p[e + i];
    } else {
        const long long* p = (const long long*)ei;
        s = (int)p[i]; d = (int)p[e + i];
    }
    int pos = atomicAdd(&g_cursor[d], 1);
    g_csr[pos] = s;
}

// ---------------- fused GEMM: tmp[node] = dis[node] * (f(rowin) @ W), fp16 ----------------

template <bool RELU_BIAS>
__global__ void __launch_bounds__(256)
mm_kernel(const float* __restrict__ in, const float* __restrict__ W,
          const float* __restrict__ b, const float* __restrict__ dis,
          __half* __restrict__ tmp, int n)
{
    __shared__ float Ws[32][32];
    __shared__ float bs[32];
    int t = threadIdx.x;
    for (int i = t; i < 1024; i += 256) Ws[i >> 5][i & 31] = W[i];
    if (RELU_BIAS && t < 32) bs[t] = b[t];
    __syncthreads();

    int node = blockIdx.x * 256 + t;
    if (node >= n) return;

    float xr[32];
    const float4* xin = reinterpret_cast<const float4*>(in + (size_t)node * HDIM);
#pragma unroll
    for (int q = 0; q < 8; q++) {
        float4 v = xin[q];
        xr[4 * q + 0] = v.x; xr[4 * q + 1] = v.y;
        xr[4 * q + 2] = v.z; xr[4 * q + 3] = v.w;
    }
    if (RELU_BIAS) {
#pragma unroll
        for (int j = 0; j < 32; j++) xr[j] = fmaxf(xr[j] + bs[j], 0.0f);
    }

    float o[32];
#pragma unroll
    for (int j = 0; j < 32; j++) o[j] = 0.0f;
#pragma unroll
    for (int k = 0; k < 32; k++) {
        float xv = xr[k];
#pragma unroll
        for (int j = 0; j < 32; j++) o[j] = fmaf(xv, Ws[k][j], o[j]);
    }

    float d = dis[node];
    uint4 u[4];
#pragma unroll
    for (int q = 0; q < 4; q++) {
        __half2 h0 = __floats2half2_rn(o[8 * q + 0] * d, o[8 * q + 1] * d);
        __half2 h1 = __floats2half2_rn(o[8 * q + 2] * d, o[8 * q + 3] * d);
        __half2 h2 = __floats2half2_rn(o[8 * q + 4] * d, o[8 * q + 5] * d);
        __half2 h3 = __floats2half2_rn(o[8 * q + 6] * d, o[8 * q + 7] * d);
        u[q].x = *reinterpret_cast<unsigned*>(&h0);
        u[q].y = *reinterpret_cast<unsigned*>(&h1);
        u[q].z = *reinterpret_cast<unsigned*>(&h2);
        u[q].w = *reinterpret_cast<unsigned*>(&h3);
    }
    uint4* tp = reinterpret_cast<uint4*>(tmp + (size_t)node * HDIM);
#pragma unroll
    for (int q = 0; q < 4; q++) tp[q] = u[q];
}

// ---------------- aggregate (pure gather, no atomics) ----------------
// 4 nodes per warp: 8-lane group per node, lane = 4 features (uint2 of half2s).
// out[d] = dis[d] * (tmp[d] + sum_src tmp[src]).  8-wide edge batches cut
// wasted unroll slots to ~27% at deg~Poisson(16); LDG.64 halves gather count.

template <bool RELU_BIAS>
__global__ void __launch_bounds__(256)
agg_kernel(const uint2* __restrict__ tmp4, float* __restrict__ out,
           const float* __restrict__ b, int n)
{
    int gid  = blockIdx.x * 256 + threadIdx.x;
    int node = gid >> 3;                 // 8 lanes per node
    int li   = threadIdx.x & 7;
    bool valid = node < n;
    if (!valid) node = n - 1;            // keep lanes converged for shfl

    int start = g_rowstart[node];
    int end   = g_rowstart[node + 1];

    uint2 sv = __ldg(&tmp4[(size_t)node * 8 + li]);        // self-loop term
    float2 a0 = __half22float2(*reinterpret_cast<__half2*>(&sv.x));
    float2 a1 = __half22float2(*reinterpret_cast<__half2*>(&sv.y));

    for (int k = start; k < end; k += 8) {
        int idx = k + li;
        int src = g_csr[idx < end ? idx : (end - 1)];
        int cnt = end - k;
#pragma unroll
        for (int j = 0; j < 8; j++) {
            int ss = __shfl_sync(0xffffffffu, src, j, 8);  // within 8-lane segment
            if (j < cnt) {
                uint2 v = __ldg(&tmp4[(size_t)ss * 8 + li]);
                float2 v0 = __half22float2(*reinterpret_cast<__half2*>(&v.x));
                float2 v1 = __half22float2(*reinterpret_cast<__half2*>(&v.y));
                a0.x += v0.x; a0.y += v0.y;
                a1.x += v1.x; a1.y += v1.y;
            }
        }
    }

    float dn = g_dis[node];
    float4 r = make_float4(a0.x * dn, a0.y * dn, a1.x * dn, a1.y * dn);
    if (RELU_BIAS) {
        float4 bb = reinterpret_cast<const float4*>(b)[li];
        r.x = fmaxf(r.x + bb.x, 0.0f);
        r.y = fmaxf(r.y + bb.y, 0.0f);
        r.z = fmaxf(r.z + bb.z, 0.0f);
        r.w = fmaxf(r.w + bb.w, 0.0f);
    }
    if (valid)
        reinterpret_cast<float4*>(out)[(size_t)node * 8 + li] = r;
}

// ---------------- launch ----------------

extern "C" void kernel_launch(void* const* d_in, const int* in_sizes, int n_in,
                              void* d_out, int out_size)
{
    const float* x   = (const float*)d_in[0];
    const void*  ei  = d_in[1];
    const float* W1  = (const float*)d_in[2];
    const float* b1  = (const float*)d_in[3];
    const float* W2  = (const float*)d_in[4];
    const float* b2  = (const float*)d_in[5];
    float*       out = (float*)d_out;

    int n = in_sizes[0] / HDIM;       // 100000
    int e = in_sizes[1] / 2;          // 1600000

    void *p_tmp, *p_acc, *p_dis;
    cudaGetSymbolAddress(&p_tmp, g_tmp);
    cudaGetSymbolAddress(&p_acc, g_acc);
    cudaGetSymbolAddress(&p_dis, g_dis);
    uint2*  tmp4 = (uint2*)p_tmp;
    __half* tmp  = (__half*)p_tmp;
    float*  acc  = (float*)p_acc;
    float*  dis  = (float*)p_dis;

    int nb_n  = (n + 255) / 256;
    int nb_n1 = (n + 256) / 256;              // covers index n for rowstart[n]
    int nb_e  = (e + 255) / 256;
    int nb_s  = (n + SCAN_B - 1) / SCAN_B;    // 98
    int nb_g  = (n * 8 + 255) / 256;          // 8 lanes per node

    // CSR build + normalization (amortized over both layers)
    count_kernel <<<nb_e, 256>>>(ei, e, n);
    scan1_kernel <<<nb_s, SCAN_B>>>(n);
    scan23_kernel<<<nb_n1, 256>>>(n, e, nb_s);
    fill_kernel  <<<nb_e, 256>>>(ei, e, n);

    // layer 1
    mm_kernel<false> <<<nb_n, 256>>>(x, W1, nullptr, dis, tmp, n);
    agg_kernel<false><<<nb_g, 256>>>(tmp4, acc, nullptr, n);

    // layer 2 (b1+ReLU fused into GEMM load; b2+ReLU fused into agg epilogue)
    mm_kernel<true>  <<<nb_n, 256>>>(acc, W2, b1, dis, tmp, n);
    agg_kernel<true> <<<nb_g, 256>>>(tmp4, out, b2, n);
}

// round 9
// speedup vs baseline: 2.8270x; 1.0833x over previous
#include <cuda_runtime.h>
#include <cuda_fp16.h>

#define NMAX   100000
#define EMAX   1600000
#define HDIM   32
#define STRIDE 64                              // padded-CSR slots per node

// Scratch (allocation-free rule: __device__ globals).
// g_deg invariant: zero at every kernel_launch entry (module-load zero-init;
// node_prep re-zeroes after consuming it each call).
__device__ int    g_deg[NMAX];                 // in-degree (excl. self-loop)
__device__ int    g_degc[NMAX];                // degree copy for agg
__device__ float  g_dis[NMAX];                 // rsqrt(deg+1)
__device__ int    g_pos[EMAX];                 // per-edge rank within dst row
__device__ int    g_csrp[(size_t)NMAX * STRIDE]; // padded CSR: src indices
__device__ int    g_ovfn;                      // overflow count
__device__ int2   g_ovf[EMAX];                 // overflow (dst, src)
__device__ __half g_tmp[(size_t)NMAX * HDIM];  // dis[i] * (f(in_i) @ W), fp16
__device__ __half g_acc16[(size_t)NMAX * HDIM];// layer-1 output, fp16

// int64 read of an int32 buffer fuses two indices -> out of [0,n) w.h.p.
// Per-block redundant detection from the first 32 int64 slots (in-bounds for
// both widths since 2E >= 64 int32 elements).
__device__ __forceinline__ int detect_is32(const void* ei, int n, int* s_is32) {
    if (threadIdx.x < 32) {
        long long v = ((const long long*)ei)[threadIdx.x];
        unsigned m = __ballot_sync(0xffffffffu, v < 0 || v >= (long long)n);
        if (threadIdx.x == 0) *s_is32 = m ? 1 : 0;
    }
    __syncthreads();
    return *s_is32;
}

// ---------------- count: degree histogram + per-edge rank ----------------

__global__ void count_kernel(const void* __restrict__ ei, int e, int n) {
    __shared__ int s_is32;
    int is32 = detect_is32(ei, n, &s_is32);
    int i = blockIdx.x * blockDim.x + threadIdx.x;
    if (i >= e) return;
    int d = is32 ? ((const int*)ei)[e + i]
                 : (int)((const long long*)ei)[e + i];
    g_pos[i] = atomicAdd(&g_deg[d], 1);        // rank = arrival order (any perm ok)
}

// ---------------- node prep: dis, degree copy, invariant restore ----------------

__global__ void node_prep_kernel(int n) {
    int i = blockIdx.x * blockDim.x + threadIdx.x;
    if (i == 0) g_ovfn = 0;
    if (i >= n) return;
    int v = g_deg[i];
    g_dis[i]  = rsqrtf((float)(v + 1));        // +1: self-loop
    g_degc[i] = v;
    g_deg[i]  = 0;                             // restore invariant for next call
}

// ---------------- fill: src into padded slot (no atomics on hot path) ----------------

__global__ void fill_kernel(const void* __restrict__ ei, int e, int n) {
    __shared__ int s_is32;
    int is32 = detect_is32(ei, n, &s_is32);
    int i = blockIdx.x * blockDim.x + threadIdx.x;
    if (i >= e) return;
    int s, d;
    if (is32) {
        const int* p = (const int*)ei;
        s = p[i]; d = p[e + i];
    } else {
        const long long* p = (const long long*)ei;
        s = (int)p[i]; d = (int)p[e + i];
    }
    int pos = g_pos[i];
    if (pos < STRIDE) {
        g_csrp[(size_t)d * STRIDE + pos] = s;
    } else {                                   // ~never on this dataset
        int k = atomicAdd(&g_ovfn, 1);
        g_ovf[k] = make_int2(d, s);
    }
}

// ---------------- fused GEMM: tmp[node] = dis[node] * (f(rowin) @ W), fp16 ----------------
// IN16: input rows are fp16 (layer-1 activations); RELU_BIAS applies b+relu on load.

template <bool IN16, bool RELU_BIAS>
__global__ void __launch_bounds__(256)
mm_kernel(const void* __restrict__ in, const float* __restrict__ W,
          const float* __restrict__ b, const float* __restrict__ dis,
          __half* __restrict__ tmp, int n)
{
    __shared__ float Ws[32][32];
    __shared__ float bs[32];
    int t = threadIdx.x;
    for (int i = t; i < 1024; i += 256) Ws[i >> 5][i & 31] = W[i];
    if (RELU_BIAS && t < 32) bs[t] = b[t];
    __syncthreads();

    int node = blockIdx.x * 256 + t;
    if (node >= n) return;

    float xr[32];
    if (IN16) {
        // 32 halves = 64 bytes = 4 x uint4; each uint4 carries 8 halves.
        const uint4* xin = reinterpret_cast<const uint4*>((const __half*)in + (size_t)node * HDIM);
#pragma unroll
        for (int q = 0; q < 4; q++) {
            uint4 u = xin[q];
            unsigned w[4] = {u.x, u.y, u.z, u.w};
#pragma unroll
            for (int j = 0; j < 4; j++) {
                float2 f = __half22float2(*reinterpret_cast<__half2*>(&w[j]));
                xr[q * 8 + j * 2 + 0] = f.x;
                xr[q * 8 + j * 2 + 1] = f.y;
            }
        }
    } else {
        const float4* xin = reinterpret_cast<const float4*>((const float*)in + (size_t)node * HDIM);
#pragma unroll
        for (int q = 0; q < 8; q++) {
            float4 v = xin[q];
            xr[4 * q + 0] = v.x; xr[4 * q + 1] = v.y;
            xr[4 * q + 2] = v.z; xr[4 * q + 3] = v.w;
        }
    }
    if (RELU_BIAS) {
#pragma unroll
        for (int j = 0; j < 32; j++) xr[j] = fmaxf(xr[j] + bs[j], 0.0f);
    }

    float o[32];
#pragma unroll
    for (int j = 0; j < 32; j++) o[j] = 0.0f;
#pragma unroll
    for (int k = 0; k < 32; k++) {
        float xv = xr[k];
#pragma unroll
        for (int j = 0; j < 32; j++) o[j] = fmaf(xv, Ws[k][j], o[j]);
    }

    float d = dis[node];
    uint4 u[4];
#pragma unroll
    for (int q = 0; q < 4; q++) {
        __half2 h0 = __floats2half2_rn(o[8 * q + 0] * d, o[8 * q + 1] * d);
        __half2 h1 = __floats2half2_rn(o[8 * q + 2] * d, o[8 * q + 3] * d);
        __half2 h2 = __floats2half2_rn(o[8 * q + 4] * d, o[8 * q + 5] * d);
        __half2 h3 = __floats2half2_rn(o[8 * q + 6] * d, o[8 * q + 7] * d);
        u[q].x = *reinterpret_cast<unsigned*>(&h0);
        u[q].y = *reinterpret_cast<unsigned*>(&h1);
        u[q].z = *reinterpret_cast<unsigned*>(&h2);
        u[q].w = *reinterpret_cast<unsigned*>(&h3);
    }
    uint4* tp = reinterpret_cast<uint4*>(tmp + (size_t)node * HDIM);
#pragma unroll
    for (int q = 0; q < 4; q++) tp[q] = u[q];
}

// ---------------- aggregate (pure gather, padded CSR) ----------------
// 4 nodes per warp: 8-lane group per node, lane = 4 features (uint2 of half2s).
// out[d] = dis[d] * (tmp[d] + sum_src tmp[src]).
// OUT16: write fp16 row without bias (layer 1). Else fp32 + bias + relu.

template <bool OUT16>
__global__ void __launch_bounds__(256)
agg_kernel(const uint2* __restrict__ tmp4, void* __restrict__ out,
           const float* __restrict__ b, int n)
{
    int gid  = blockIdx.x * 256 + threadIdx.x;
    int node = gid >> 3;                 // 8 lanes per node
    int li   = threadIdx.x & 7;
    bool valid = node < n;
    if (!valid) node = n - 1;            // keep lanes converged for shfl

    int deg = g_degc[node];
    int end = deg < STRIDE ? deg : STRIDE;
    const int* row = g_csrp + (size_t)node * STRIDE;

    uint2 sv = __ldg(&tmp4[(size_t)node * 8 + li]);        // self-loop term
    float2 a0 = __half22float2(*reinterpret_cast<__half2*>(&sv.x));
    float2 a1 = __half22float2(*reinterpret_cast<__half2*>(&sv.y));

    for (int k = 0; k < end; k += 8) {
        int idx = k + li;
        int src = row[idx < end ? idx : (end - 1)];
        int cnt = end - k;
#pragma unroll
        for (int j = 0; j < 8; j++) {
            int ss = __shfl_sync(0xffffffffu, src, j, 8);  // within 8-lane segment
            if (j < cnt) {
                uint2 v = __ldg(&tmp4[(size_t)ss * 8 + li]);
                float2 v0 = __half22float2(*reinterpret_cast<__half2*>(&v.x));
                float2 v1 = __half22float2(*reinterpret_cast<__half2*>(&v.y));
                a0.x += v0.x; a0.y += v0.y;
                a1.x += v1.x; a1.y += v1.y;
            }
        }
    }

    if (deg > STRIDE) {                  // overflow path: ~never taken
        int c = g_ovfn;
        for (int i = 0; i < c; i++) {
            int2 o = g_ovf[i];
            if (o.x == node) {
                uint2 v = __ldg(&tmp4[(size_t)o.y * 8 + li]);
                float2 v0 = __half22float2(*reinterpret_cast<__half2*>(&v.x));
                float2 v1 = __half22float2(*reinterpret_cast<__half2*>(&v.y));
                a0.x += v0.x; a0.y += v0.y;
                a1.x += v1.x; a1.y += v1.y;
            }
        }
    }

    float dn = g_dis[node];
    if (!valid) return;
    if (OUT16) {
        __half2 h0 = __floats2half2_rn(a0.x * dn, a0.y * dn);
        __half2 h1 = __floats2half2_rn(a1.x * dn, a1.y * dn);
        uint2 u;
        u.x = *reinterpret_cast<unsigned*>(&h0);
        u.y = *reinterpret_cast<unsigned*>(&h1);
        reinterpret_cast<uint2*>(out)[(size_t)node * 8 + li] = u;
    } else {
        float4 bb = reinterpret_cast<const float4*>(b)[li];
        float4 r = make_float4(fmaxf(a0.x * dn + bb.x, 0.0f),
                               fmaxf(a0.y * dn + bb.y, 0.0f),
                               fmaxf(a1.x * dn + bb.z, 0.0f),
                               fmaxf(a1.y * dn + bb.w, 0.0f));
        reinterpret_cast<float4*>(out)[(size_t)node * 8 + li] = r;
    }
}

// ---------------- launch ----------------

extern "C" void kernel_launch(void* const* d_in, const int* in_sizes, int n_in,
                              void* d_out, int out_size)
{
    const float* x   = (const float*)d_in[0];
    const void*  ei  = d_in[1];
    const float* W1  = (const float*)d_in[2];
    const float* b1  = (const float*)d_in[3];
    const float* W2  = (const float*)d_in[4];
    const float* b2  = (const float*)d_in[5];
    float*       out = (float*)d_out;

    int n = in_sizes[0] / HDIM;       // 100000
    int e = in_sizes[1] / 2;          // 1600000

    void *p_tmp, *p_acc, *p_dis;
    cudaGetSymbolAddress(&p_tmp, g_tmp);
    cudaGetSymbolAddress(&p_acc, g_acc16);
    cudaGetSymbolAddress(&p_dis, g_dis);
    uint2*  tmp4  = (uint2*)p_tmp;
    __half* tmp   = (__half*)p_tmp;
    __half* acc16 = (__half*)p_acc;
    float*  dis   = (float*)p_dis;

    int nb_n = (n + 255) / 256;
    int nb_e = (e + 255) / 256;
    int nb_g = (n * 8 + 255) / 256;           // 8 lanes per node

    // padded-CSR build + normalization (amortized over both layers)
    count_kernel    <<<nb_e, 256>>>(ei, e, n);
    node_prep_kernel<<<nb_n, 256>>>(n);
    fill_kernel     <<<nb_e, 256>>>(ei, e, n);

    // layer 1
    mm_kernel<false, false><<<nb_n, 256>>>(x, W1, nullptr, dis, tmp, n);
    agg_kernel<true>       <<<nb_g, 256>>>(tmp4, acc16, nullptr, n);

    // layer 2 (b1+ReLU fused into GEMM load; b2+ReLU fused into agg epilogue)
    mm_kernel<true, true>  <<<nb_n, 256>>>(acc16, W2, b1, dis, tmp, n);
    agg_kernel<false>      <<<nb_g, 256>>>(tmp4, out, b2, n);
}

// round 10
// speedup vs baseline: 2.9414x; 1.0404x over previous
#include <cuda_runtime.h>
#include <cuda_fp16.h>

#define NMAX   100000
#define EMAX   1600000
#define HDIM   32
#define STRIDE 64                              // padded-CSR slots per node

// Scratch (allocation-free rule: __device__ globals).
// Invariant: g_deg and g_ovfn are zero at every kernel_launch entry
// (module-load zero-init; node_prep restores after consuming them).
__device__ int    g_deg[NMAX];                 // in-degree (excl. self-loop)
__device__ int    g_degc[NMAX];                // degree copy for agg
__device__ float  g_dis[NMAX];                 // rsqrt(deg+1)
__device__ int    g_csrp[(size_t)NMAX * STRIDE]; // padded CSR: src indices
__device__ int    g_ovfn;                      // overflow count (build)
__device__ int    g_ovfc;                      // overflow count (stable copy)
__device__ int2   g_ovf[EMAX];                 // overflow (dst, src)
__device__ __half g_tmp[(size_t)NMAX * HDIM];  // dis[i] * (f(in_i) @ W), fp16
__device__ __half g_acc16[(size_t)NMAX * HDIM];// layer-1 output, fp16

// int64 read of an int32 buffer fuses two indices -> out of [0,n) w.h.p.
// Per-block redundant detection from the first 32 int64 slots (in-bounds for
// both widths since 2E >= 64 int32 elements).
__device__ __forceinline__ int detect_is32(const void* ei, int n, int* s_is32) {
    if (threadIdx.x < 32) {
        long long v = ((const long long*)ei)[threadIdx.x];
        unsigned m = __ballot_sync(0xffffffffu, v < 0 || v >= (long long)n);
        if (threadIdx.x == 0) *s_is32 = m ? 1 : 0;
    }
    __syncthreads();
    return *s_is32;
}

// ---------------- build: degree histogram + padded-CSR fill in ONE pass ----------------
// Slot assignment needs only the atomic rank, not completed counts.

__global__ void build_kernel(const void* __restrict__ ei, int e, int n) {
    __shared__ int s_is32;
    int is32 = detect_is32(ei, n, &s_is32);
    int i = blockIdx.x * blockDim.x + threadIdx.x;
    if (i >= e) return;
    int s, d;
    if (is32) {
        const int* p = (const int*)ei;
        s = p[i]; d = p[e + i];
    } else {
        const long long* p = (const long long*)ei;
        s = (int)p[i]; d = (int)p[e + i];
    }
    int pos = atomicAdd(&g_deg[d], 1);         // rank = slot (any perm ok)
    if (pos < STRIDE) {
        g_csrp[(size_t)d * STRIDE + pos] = s;
    } else {                                   // ~never on this dataset
        int k = atomicAdd(&g_ovfn, 1);
        g_ovf[k] = make_int2(d, s);
    }
}

// ---------------- node prep: dis, degree copy, invariant restore ----------------

__global__ void node_prep_kernel(int n) {
    int i = blockIdx.x * blockDim.x + threadIdx.x;
    if (i == 0) { g_ovfc = g_ovfn; g_ovfn = 0; }
    if (i >= n) return;
    int v = g_deg[i];
    g_dis[i]  = rsqrtf((float)(v + 1));        // +1: self-loop
    g_degc[i] = v;
    g_deg[i]  = 0;                             // restore invariant for next call
}

// ---------------- fused GEMM: tmp[node] = dis[node] * (f(rowin) @ W), fp16 ----------------
// 2 threads per node (j-halves of 16): regs ~60 -> 4 blocks/SM, occ 50%.
// IN16: input rows are fp16; RELU_BIAS applies b+relu on load.

template <bool IN16, bool RELU_BIAS>
__global__ void __launch_bounds__(256)
mm_kernel(const void* __restrict__ in, const float* __restrict__ W,
          const float* __restrict__ b, const float* __restrict__ dis,
          __half* __restrict__ tmp, int n)
{
    __shared__ float Ws[32][32];
    __shared__ float bs[32];
    int t = threadIdx.x;
    for (int i = t; i < 1024; i += 256) Ws[i >> 5][i & 31] = W[i];
    if (RELU_BIAS && t < 32) bs[t] = b[t];
    __syncthreads();

    int node = blockIdx.x * 128 + (t >> 1);
    int half = t & 1;                      // output j-range: half*16 .. half*16+15
    if (node >= n) return;

    float xr[32];
    if (IN16) {
        const uint4* xin = reinterpret_cast<const uint4*>((const __half*)in + (size_t)node * HDIM);
#pragma unroll
        for (int q = 0; q < 4; q++) {
            uint4 u = xin[q];
            unsigned w[4] = {u.x, u.y, u.z, u.w};
#pragma unroll
            for (int j = 0; j < 4; j++) {
                float2 f = __half22float2(*reinterpret_cast<__half2*>(&w[j]));
                xr[q * 8 + j * 2 + 0] = f.x;
                xr[q * 8 + j * 2 + 1] = f.y;
            }
        }
    } else {
        const float4* xin = reinterpret_cast<const float4*>((const float*)in + (size_t)node * HDIM);
#pragma unroll
        for (int q = 0; q < 8; q++) {
            float4 v = xin[q];
            xr[4 * q + 0] = v.x; xr[4 * q + 1] = v.y;
            xr[4 * q + 2] = v.z; xr[4 * q + 3] = v.w;
        }
    }
    if (RELU_BIAS) {
#pragma unroll
        for (int j = 0; j < 32; j++) xr[j] = fmaxf(xr[j] + bs[j], 0.0f);
    }

    int jb = half * 16;
    float o[16];
#pragma unroll
    for (int j = 0; j < 16; j++) o[j] = 0.0f;
#pragma unroll
    for (int k = 0; k < 32; k++) {
        float xv = xr[k];
#pragma unroll
        for (int j = 0; j < 16; j++) o[j] = fmaf(xv, Ws[k][jb + j], o[j]);
    }

    float d = dis[node];
    uint4 u[2];
#pragma unroll
    for (int q = 0; q < 2; q++) {
        __half2 h0 = __floats2half2_rn(o[8 * q + 0] * d, o[8 * q + 1] * d);
        __half2 h1 = __floats2half2_rn(o[8 * q + 2] * d, o[8 * q + 3] * d);
        __half2 h2 = __floats2half2_rn(o[8 * q + 4] * d, o[8 * q + 5] * d);
        __half2 h3 = __floats2half2_rn(o[8 * q + 6] * d, o[8 * q + 7] * d);
        u[q].x = *reinterpret_cast<unsigned*>(&h0);
        u[q].y = *reinterpret_cast<unsigned*>(&h1);
        u[q].z = *reinterpret_cast<unsigned*>(&h2);
        u[q].w = *reinterpret_cast<unsigned*>(&h3);
    }
    uint4* tp = reinterpret_cast<uint4*>(tmp + (size_t)node * HDIM + jb);
    tp[0] = u[0];
    tp[1] = u[1];
}

// ---------------- aggregate (pure gather, padded CSR) ----------------
// 4 nodes per warp: 8-lane group per node, lane = 4 features (uint2 of half2s).
// out[d] = dis[d] * (tmp[d] + sum_src tmp[src]).
// OUT16: write fp16 row without bias (layer 1). Else fp32 + bias + relu.

template <bool OUT16>
__global__ void __launch_bounds__(256)
agg_kernel(const uint2* __restrict__ tmp4, void* __restrict__ out,
           const float* __restrict__ b, int n)
{
    int gid  = blockIdx.x * 256 + threadIdx.x;
    int node = gid >> 3;                 // 8 lanes per node
    int li   = threadIdx.x & 7;
    bool valid = node < n;
    if (!valid) node = n - 1;            // keep lanes converged for shfl

    int deg = g_degc[node];
    int end = deg < STRIDE ? deg : STRIDE;
    const int* row = g_csrp + (size_t)node * STRIDE;

    uint2 sv = __ldg(&tmp4[(size_t)node * 8 + li]);        // self-loop term
    float2 a0 = __half22float2(*reinterpret_cast<__half2*>(&sv.x));
    float2 a1 = __half22float2(*reinterpret_cast<__half2*>(&sv.y));

    for (int k = 0; k < end; k += 8) {
        int idx = k + li;
        int src = row[idx < end ? idx : (end - 1)];
        int cnt = end - k;
#pragma unroll
        for (int j = 0; j < 8; j++) {
            int ss = __shfl_sync(0xffffffffu, src, j, 8);  // within 8-lane segment
            if (j < cnt) {
                uint2 v = __ldg(&tmp4[(size_t)ss * 8 + li]);
                float2 v0 = __half22float2(*reinterpret_cast<__half2*>(&v.x));
                float2 v1 = __half22float2(*reinterpret_cast<__half2*>(&v.y));
                a0.x += v0.x; a0.y += v0.y;
                a1.x += v1.x; a1.y += v1.y;
            }
        }
    }

    if (deg > STRIDE) {                  // overflow path: ~never taken
        int c = g_ovfc;
        for (int i = 0; i < c; i++) {
            int2 o = g_ovf[i];
            if (o.x == node) {
                uint2 v = __ldg(&tmp4[(size_t)o.y * 8 + li]);
                float2 v0 = __half22float2(*reinterpret_cast<__half2*>(&v.x));
                float2 v1 = __half22float2(*reinterpret_cast<__half2*>(&v.y));
                a0.x += v0.x; a0.y += v0.y;
                a1.x += v1.x; a1.y += v1.y;
            }
        }
    }

    float dn = g_dis[node];
    if (!valid) return;
    if (OUT16) {
        __half2 h0 = __floats2half2_rn(a0.x * dn, a0.y * dn);
        __half2 h1 = __floats2half2_rn(a1.x * dn, a1.y * dn);
        uint2 u;
        u.x = *reinterpret_cast<unsigned*>(&h0);
        u.y = *reinterpret_cast<unsigned*>(&h1);
        reinterpret_cast<uint2*>(out)[(size_t)node * 8 + li] = u;
    } else {
        float4 bb = reinterpret_cast<const float4*>(b)[li];
        float4 r = make_float4(fmaxf(a0.x * dn + bb.x, 0.0f),
                               fmaxf(a0.y * dn + bb.y, 0.0f),
                               fmaxf(a1.x * dn + bb.z, 0.0f),
                               fmaxf(a1.y * dn + bb.w, 0.0f));
        reinterpret_cast<float4*>(out)[(size_t)node * 8 + li] = r;
    }
}

// ---------------- launch ----------------

extern "C" void kernel_launch(void* const* d_in, const int* in_sizes, int n_in,
                              void* d_out, int out_size)
{
    const float* x   = (const float*)d_in[0];
    const void*  ei  = d_in[1];
    const float* W1  = (const float*)d_in[2];
    const float* b1  = (const float*)d_in[3];
    const float* W2  = (const float*)d_in[4];
    const float* b2  = (const float*)d_in[5];
    float*       out = (float*)d_out;

    int n = in_sizes[0] / HDIM;       // 100000
    int e = in_sizes[1] / 2;          // 1600000

    void *p_tmp, *p_acc, *p_dis;
    cudaGetSymbolAddress(&p_tmp, g_tmp);
    cudaGetSymbolAddress(&p_acc, g_acc16);
    cudaGetSymbolAddress(&p_dis, g_dis);
    uint2*  tmp4  = (uint2*)p_tmp;
    __half* tmp   = (__half*)p_tmp;
    __half* acc16 = (__half*)p_acc;
    float*  dis   = (float*)p_dis;

    int nb_n = (n + 255) / 256;
    int nb_e = (e + 255) / 256;
    int nb_m = (n + 127) / 128;               // 2 threads per node
    int nb_g = (n * 8 + 255) / 256;           // 8 lanes per node

    // padded-CSR build + normalization (amortized over both layers)
    build_kernel    <<<nb_e, 256>>>(ei, e, n);
    node_prep_kernel<<<nb_n, 256>>>(n);

    // layer 1
    mm_kernel<false, false><<<nb_m, 256>>>(x, W1, nullptr, dis, tmp, n);
    agg_kernel<true>       <<<nb_g, 256>>>(tmp4, acc16, nullptr, n);

    // layer 2 (b1+ReLU fused into GEMM load; b2+ReLU fused into agg epilogue)
    mm_kernel<true, true>  <<<nb_m, 256>>>(acc16, W2, b1, dis, tmp, n);
    agg_kernel<false>      <<<nb_g, 256>>>(tmp4, out, b2, n);
}